// round 6
// baseline (speedup 1.0000x reference)
#include <cuda_runtime.h>
#include <math.h>

#define N_NODES 20000
#define N_EDGES 320000
#define IN_DIM  64
#define EMB     128
#define OUT_DIM 10
#define HID     512
#define RATIO_F 0.25
#define EPSF    1e-20f

// ---------------- scratch (static, no allocs) ----------------
__device__ float g_h0[N_NODES*EMB];
__device__ float g_h1[N_NODES*EMB];
__device__ float g_agg[N_NODES*EMB];
__device__ float g_Afac[N_NODES*HID];
__device__ float g_Bfac[N_NODES*HID];
__device__ float g_pe[N_EDGES];
__device__ float g_delta0[N_EDGES];
__device__ float g_T[N_EDGES];
__device__ int   g_counts[N_NODES];
__device__ int   g_rowptr[N_NODES+1];
__device__ int   g_cursor[N_NODES];
__device__ int   g_srcs[N_EDGES];
__device__ int   g_eids[N_EDGES];
__device__ double g_sum, g_sumsq;
__device__ float  g_pmin, g_pmax;
__device__ float  g_mean, g_invstd, g_csum;
__device__ double g_Ssum[32];
__device__ unsigned int g_barc;
__device__ volatile unsigned int g_barg;
__device__ double g_colsum[EMB];

// ---------------- init ----------------
__global__ void init_kernel() {
    int i = blockIdx.x*blockDim.x + threadIdx.x;
    int nt = gridDim.x*blockDim.x;
    for (int k = i; k < N_NODES; k += nt) { g_counts[k] = 0; g_cursor[k] = 0; }
    if (i < EMB) g_colsum[i] = 0.0;
    if (i < 32)  g_Ssum[i]   = 0.0;
    if (i == 0) {
        g_sum = 0.0; g_sumsq = 0.0;
        g_pmin =  3.0e38f; g_pmax = -3.0e38f;
        g_barc = 0u; g_barg = 0u;
    }
}

// ---------------- CSR build ----------------
__global__ void hist_kernel(const int* __restrict__ dst) {
    int i = blockIdx.x*blockDim.x + threadIdx.x;
    int nt = gridDim.x*blockDim.x;
    for (int e = i; e < N_EDGES; e += nt) atomicAdd(&g_counts[dst[e]], 1);
}

__global__ void scan_kernel() {
    __shared__ int s[1024];
    const int CH = (N_NODES + 1023) / 1024;  // 20
    int t = threadIdx.x;
    int lsum = 0;
    for (int i = 0; i < CH; i++) {
        int idx = t*CH + i;
        if (idx < N_NODES) lsum += g_counts[idx];
    }
    s[t] = lsum; __syncthreads();
    for (int off = 1; off < 1024; off <<= 1) {
        int v = (t >= off) ? s[t-off] : 0;
        __syncthreads();
        s[t] += v;
        __syncthreads();
    }
    int run = s[t] - lsum;   // exclusive prefix
    for (int i = 0; i < CH; i++) {
        int idx = t*CH + i;
        if (idx < N_NODES) { g_rowptr[idx] = run; run += g_counts[idx]; }
    }
    if (t == 1023) g_rowptr[N_NODES] = s[1023];
}

__global__ void fill_kernel(const int* __restrict__ src, const int* __restrict__ dst) {
    int i = blockIdx.x*blockDim.x + threadIdx.x;
    int nt = gridDim.x*blockDim.x;
    for (int e = i; e < N_EDGES; e += nt) {
        int d = dst[e];
        int pos = atomicAdd(&g_cursor[d], 1);
        int slot = g_rowptr[d] + pos;
        g_srcs[slot] = src[e];
        g_eids[slot] = e;
    }
}

// ---------------- aggregation: out[n,:] = sum_{in-edges} w_e * h[src_e,:] ----------------
__global__ void agg_kernel(const float* __restrict__ h, float* __restrict__ out,
                           const float* __restrict__ Tw, int dim) {
    int n = blockIdx.x;
    int t = threadIdx.x;
    if (t >= dim) return;
    int beg = g_rowptr[n], end = g_rowptr[n+1];
    float acc = 0.f;
    if (Tw) {
        for (int j = beg; j < end; j++)
            acc += Tw[g_eids[j]] * h[g_srcs[j]*dim + t];
    } else {
        for (int j = beg; j < end; j++)
            acc += h[g_srcs[j]*dim + t];
    }
    out[n*dim + t] = acc;
}

// ---------------- GEMM: C = maybe_relu((X [+Y]) @ W [+bias]) ----------------
// BM=64 BN=64 BK=16, 128 threads, TM=8 TN=4
__global__ void gemm_fused(const float* __restrict__ X, const float* __restrict__ Y,
                           const float* __restrict__ W, const float* __restrict__ bias,
                           float* __restrict__ C, int M, int K, int N, int do_relu) {
    __shared__ __align__(16) float Xs[64][17];
    __shared__ __align__(16) float Ws[16][64];
    int tid = threadIdx.x;
    int tx = tid & 15, ty = tid >> 4;
    int row0 = blockIdx.y * 64;
    int col0 = blockIdx.x * 64;
    float acc[8][4];
#pragma unroll
    for (int i = 0; i < 8; i++)
#pragma unroll
        for (int j = 0; j < 4; j++) acc[i][j] = 0.f;

    for (int k0 = 0; k0 < K; k0 += 16) {
#pragma unroll
        for (int i = 0; i < 8; i++) {
            int idx = tid + i*128;
            int r = idx >> 4, c = idx & 15;
            int gr = row0 + r;
            float v = 0.f;
            if (gr < M) {
                v = X[gr*K + k0 + c];
                if (Y) v += Y[gr*K + k0 + c];
            }
            Xs[r][c] = v;
        }
#pragma unroll
        for (int i = 0; i < 8; i++) {
            int idx = tid + i*128;
            int r = idx >> 6, c = idx & 63;
            Ws[r][c] = W[(k0 + r)*N + col0 + c];
        }
        __syncthreads();
#pragma unroll
        for (int kk = 0; kk < 16; kk++) {
            float a[8];
            float4 b4 = *reinterpret_cast<const float4*>(&Ws[kk][tx*4]);
            float b[4] = {b4.x, b4.y, b4.z, b4.w};
#pragma unroll
            for (int i = 0; i < 8; i++) a[i] = Xs[ty*8 + i][kk];
#pragma unroll
            for (int i = 0; i < 8; i++)
#pragma unroll
                for (int j = 0; j < 4; j++) acc[i][j] = fmaf(a[i], b[j], acc[i][j]);
        }
        __syncthreads();
    }
#pragma unroll
    for (int i = 0; i < 8; i++) {
        int gr = row0 + ty*8 + i;
        if (gr < M) {
#pragma unroll
            for (int j = 0; j < 4; j++) {
                int gc = col0 + tx*4 + j;
                float v = acc[i][j];
                if (bias) v += bias[gc];
                if (do_relu) v = fmaxf(v, 0.f);
                C[gr*N + gc] = v;
            }
        }
    }
}

// ---------------- edge attention: pe[e] = relu(A[src]+B[dst]+b1) . W2 + b2 ----------------
__global__ void edge_pe_kernel(const int* __restrict__ src, const int* __restrict__ dst,
                               const float* __restrict__ b1, const float* __restrict__ W2,
                               const float* __restrict__ b2) {
    int gid = blockIdx.x*blockDim.x + threadIdx.x;
    int lane = threadIdx.x & 31;
    int warp = gid >> 5;
    int nwarps = (gridDim.x*blockDim.x) >> 5;
    for (int e = warp; e < N_EDGES; e += nwarps) {
        int s = src[e], d = dst[e];
        const float4* Ap = reinterpret_cast<const float4*>(&g_Afac[s*HID]);
        const float4* Bp = reinterpret_cast<const float4*>(&g_Bfac[d*HID]);
        const float4* b1p = reinterpret_cast<const float4*>(b1);
        const float4* W2p = reinterpret_cast<const float4*>(W2);
        float acc = 0.f;
#pragma unroll
        for (int j = 0; j < 4; j++) {
            int idx = lane + 32*j;
            float4 a = Ap[idx], b = Bp[idx], bb = b1p[idx], w = W2p[idx];
            float z0 = fmaxf(a.x + b.x + bb.x, 0.f);
            float z1 = fmaxf(a.y + b.y + bb.y, 0.f);
            float z2 = fmaxf(a.z + b.z + bb.z, 0.f);
            float z3 = fmaxf(a.w + b.w + bb.w, 0.f);
            acc += z0*w.x + z1*w.y + z2*w.z + z3*w.w;
        }
#pragma unroll
        for (int off = 16; off > 0; off >>= 1)
            acc += __shfl_xor_sync(0xffffffffu, acc, off);
        if (lane == 0) g_pe[e] = acc + b2[0];
    }
}

// ---------------- pe stats ----------------
__device__ void atomicMaxF(float* addr, float v) {
    int* ai = (int*)addr; int old = *ai;
    while (__int_as_float(old) < v) {
        int assumed = old;
        old = atomicCAS(ai, assumed, __float_as_int(v));
        if (old == assumed) break;
    }
}
__device__ void atomicMinF(float* addr, float v) {
    int* ai = (int*)addr; int old = *ai;
    while (__int_as_float(old) > v) {
        int assumed = old;
        old = atomicCAS(ai, assumed, __float_as_int(v));
        if (old == assumed) break;
    }
}

__global__ void stats_kernel() {
    __shared__ double ssum[256], ssq[256];
    __shared__ float smn[256], smx[256];
    int i = blockIdx.x*blockDim.x + threadIdx.x;
    int nt = gridDim.x*blockDim.x;
    double lsum = 0.0, lsq = 0.0;
    float mn = 3.0e38f, mx = -3.0e38f;
    for (int e = i; e < N_EDGES; e += nt) {
        float p = g_pe[e];
        lsum += p; lsq += (double)p*p;
        mn = fminf(mn, p); mx = fmaxf(mx, p);
    }
    int t = threadIdx.x;
    ssum[t] = lsum; ssq[t] = lsq; smn[t] = mn; smx[t] = mx;
    __syncthreads();
    for (int off = 128; off > 0; off >>= 1) {
        if (t < off) {
            ssum[t] += ssum[t+off]; ssq[t] += ssq[t+off];
            smn[t] = fminf(smn[t], smn[t+off]); smx[t] = fmaxf(smx[t], smx[t+off]);
        }
        __syncthreads();
    }
    if (t == 0) {
        atomicAdd(&g_sum, ssum[0]);
        atomicAdd(&g_sumsq, ssq[0]);
        atomicMinF(&g_pmin, smn[0]);
        atomicMaxF(&g_pmax, smx[0]);
    }
}

__global__ void finalize_kernel() {
    double mean = g_sum / (double)N_EDGES;
    double var = (g_sumsq - g_sum*g_sum/(double)N_EDGES) / (double)(N_EDGES - 1);
    double istd = 1.0 / sqrt(var);
    g_mean = (float)mean;
    g_invstd = (float)istd;
    g_csum = (float)(((double)g_pmin + (double)g_pmax - 2.0*mean) * istd);  // s_min + s_max (standardized)
}

// ---------------- delta0 = 2*(atts + gumbel) - (s_min+s_max) ----------------
__global__ void delta0_kernel(const float* __restrict__ u) {
    int i = blockIdx.x*blockDim.x + threadIdx.x;
    int nt = gridDim.x*blockDim.x;
    float mean = g_mean, istd = g_invstd, cs = g_csum;
    for (int e = i; e < N_EDGES; e += nt) {
        float att = (g_pe[e] - mean) * istd;
        float g = -logf(-logf(u[e] + EPSF) + EPSF);
        float d = att + g;            // NOISE = 1
        g_delta0[e] = 2.f*d - cs;     // TEMP = 1
    }
}

// ---------------- Sinkhorn (collapsed to scalar-offset iteration) ----------------
#define SK_BLOCKS 132
#define SK_THREADS 256
#define SK_PER 10

__global__ void sinkhorn_kernel() {
    const int stride = SK_BLOCKS * SK_THREADS;
    const int tid = blockIdx.x*blockDim.x + threadIdx.x;
    float dv[SK_PER];
#pragma unroll
    for (int i = 0; i < SK_PER; i++) {
        int e = tid + i*stride;
        dv[i] = (e < N_EDGES) ? g_delta0[e] : -1.0e30f;  // sigmoid -> 0 for pad
    }
    __shared__ double sred[SK_THREADS];
    double K = 0.0;
    double Sfin = 0.0;
    for (int it = 0; it < 30; it++) {
        float Kf = (float)K;
        double s = 0.0;
#pragma unroll
        for (int i = 0; i < SK_PER; i++)
            s += 1.0f / (1.0f + __expf(-(dv[i] + Kf)));
        sred[threadIdx.x] = s;
        __syncthreads();
        for (int off = SK_THREADS/2; off > 0; off >>= 1) {
            if (threadIdx.x < off) sred[threadIdx.x] += sred[threadIdx.x + off];
            __syncthreads();
        }
        if (threadIdx.x == 0) atomicAdd(&g_Ssum[it], sred[0]);
        // grid barrier, generation it+1
        __threadfence();
        __syncthreads();
        if (threadIdx.x == 0) {
            unsigned my = atomicAdd(&g_barc, 1u);
            if (my == SK_BLOCKS - 1) {
                g_barc = 0u;
                __threadfence();
                g_barg = (unsigned)(it + 1);
            } else {
                while (g_barg < (unsigned)(it + 1)) { }
            }
        }
        __syncthreads();
        __threadfence();
        double S1 = ((volatile double*)g_Ssum)[it];
        if (it == 29) { Sfin = S1; break; }
        double S0 = (double)N_EDGES - S1;
        K += log(S0 / S1) + log(RATIO_F / (1.0 - RATIO_F));
        __syncthreads();
    }
    float Kf = (float)K;
    float scale = (float)(((double)N_EDGES * RATIO_F) / Sfin);  // exp(r1)/S1_final
#pragma unroll
    for (int i = 0; i < SK_PER; i++) {
        int e = tid + i*stride;
        if (e < N_EDGES)
            g_T[e] = scale / (1.f + __expf(-(dv[i] + Kf)));
    }
}

// ---------------- mean pool + head ----------------
__global__ void colsum_kernel(const float* __restrict__ h) {
    int t = threadIdx.x;  // 128
    double acc = 0.0;
    for (int r = blockIdx.x; r < N_NODES; r += gridDim.x)
        acc += h[r*EMB + t];
    atomicAdd(&g_colsum[t], acc);
}

__global__ void head_kernel(const float* __restrict__ head_W,
                            const float* __restrict__ head_b,
                            float* __restrict__ out) {
    __shared__ float rep[EMB];
    int t = threadIdx.x;
    rep[t] = (float)(g_colsum[t] / (double)N_NODES);
    __syncthreads();
    if (t < OUT_DIM) {
        float a = head_b[t];
        for (int d = 0; d < EMB; d++) a += rep[d] * head_W[d*OUT_DIM + t];
        out[t] = a;
    }
}

// ---------------- launch ----------------
extern "C" void kernel_launch(void* const* d_in, const int* in_sizes, int n_in,
                              void* d_out, int out_size) {
    const float* x       = (const float*)d_in[0];
    const int*   ei      = (const int*)  d_in[1];
    const float* u       = (const float*)d_in[2];
    const float* enc_W0  = (const float*)d_in[3];
    const float* enc_b0  = (const float*)d_in[4];
    const float* enc_W   = (const float*)d_in[5];
    const float* enc_b   = (const float*)d_in[6];
    const float* ea_W1   = (const float*)d_in[7];
    const float* ea_b1   = (const float*)d_in[8];
    const float* ea_W2   = (const float*)d_in[9];
    const float* ea_b2   = (const float*)d_in[10];
    const float* cls_W0  = (const float*)d_in[11];
    const float* cls_b0  = (const float*)d_in[12];
    const float* cls_W   = (const float*)d_in[13];
    const float* cls_b   = (const float*)d_in[14];
    const float* head_W  = (const float*)d_in[15];
    const float* head_b  = (const float*)d_in[16];
    const int* src = ei;
    const int* dst = ei + N_EDGES;

    // CRITICAL (GB300/ATS): __device__ symbols passed as kernel args from host
    // code decay to the HOST shadow address and silently read host memory via
    // NVLink-C2C instead of trapping. Resolve real device addresses explicitly.
    float *p_h0, *p_h1, *p_agg, *p_Afac, *p_Bfac, *p_T;
    cudaGetSymbolAddress((void**)&p_h0,   g_h0);
    cudaGetSymbolAddress((void**)&p_h1,   g_h1);
    cudaGetSymbolAddress((void**)&p_agg,  g_agg);
    cudaGetSymbolAddress((void**)&p_Afac, g_Afac);
    cudaGetSymbolAddress((void**)&p_Bfac, g_Bfac);
    cudaGetSymbolAddress((void**)&p_T,    g_T);

    const dim3 gemm_grid128(EMB/64, (N_NODES + 63)/64);   // N=128
    const dim3 gemm_grid512(HID/64, (N_NODES + 63)/64);   // N=512

    init_kernel<<<80, 256>>>();
    hist_kernel<<<640, 256>>>(dst);
    scan_kernel<<<1, 1024>>>();
    fill_kernel<<<640, 256>>>(src, dst);

    // ----- encoder GIN stack (att = 1) -----
    agg_kernel<<<N_NODES, IN_DIM>>>(x, p_agg, nullptr, IN_DIM);
    gemm_fused<<<gemm_grid128, 128>>>(x, p_agg, enc_W0, enc_b0, p_h0,
                                      N_NODES, IN_DIM, EMB, 1);
    float* hcur = p_h0; float* hnxt = p_h1;
    for (int l = 0; l < 4; l++) {
        agg_kernel<<<N_NODES, EMB>>>(hcur, p_agg, nullptr, EMB);
        gemm_fused<<<gemm_grid128, 128>>>(hcur, p_agg, enc_W + l*EMB*EMB,
                                          enc_b + l*EMB, hnxt,
                                          N_NODES, EMB, EMB, 1);
        float* t = hcur; hcur = hnxt; hnxt = t;
    }

    // ----- edge attention (factored): A = h@W1[:128], B = h@W1[128:] -----
    gemm_fused<<<gemm_grid512, 128>>>(hcur, nullptr, ea_W1, nullptr, p_Afac,
                                      N_NODES, EMB, HID, 0);
    gemm_fused<<<gemm_grid512, 128>>>(hcur, nullptr, ea_W1 + EMB*HID, nullptr, p_Bfac,
                                      N_NODES, EMB, HID, 0);
    edge_pe_kernel<<<2000, 256>>>(src, dst, ea_b1, ea_W2, ea_b2);

    stats_kernel<<<640, 256>>>();
    finalize_kernel<<<1, 1>>>();
    delta0_kernel<<<640, 256>>>(u);
    sinkhorn_kernel<<<SK_BLOCKS, SK_THREADS>>>();

    // ----- classifier GIN stack (att = T) -----
    agg_kernel<<<N_NODES, IN_DIM>>>(x, p_agg, p_T, IN_DIM);
    gemm_fused<<<gemm_grid128, 128>>>(x, p_agg, cls_W0, cls_b0, p_h0,
                                      N_NODES, IN_DIM, EMB, 1);
    hcur = p_h0; hnxt = p_h1;
    for (int l = 0; l < 4; l++) {
        agg_kernel<<<N_NODES, EMB>>>(hcur, p_agg, p_T, EMB);
        gemm_fused<<<gemm_grid128, 128>>>(hcur, p_agg, cls_W + l*EMB*EMB,
                                          cls_b + l*EMB, hnxt,
                                          N_NODES, EMB, EMB, 1);
        float* t = hcur; hcur = hnxt; hnxt = t;
    }

    // ----- mean pool + head -----
    colsum_kernel<<<160, EMB>>>(hcur);
    head_kernel<<<1, EMB>>>(head_W, head_b, (float*)d_out);
}

// round 7
// speedup vs baseline: 1.1219x; 1.1219x over previous
#include <cuda_runtime.h>
#include <math.h>

#define N_NODES 20000
#define N_EDGES 320000
#define IN_DIM  64
#define EMB     128
#define OUT_DIM 10
#define HID     512
#define RATIO_F 0.25
#define EPSF    1e-20f

// ---------------- scratch (static, no allocs) ----------------
__device__ float g_h0[N_NODES*EMB];
__device__ float g_h1[N_NODES*EMB];
__device__ float g_agg[N_NODES*EMB];
__device__ float g_Afac[N_NODES*HID];
__device__ float g_Bfac[N_NODES*HID];
__device__ float g_pe[N_EDGES];
__device__ float g_delta0[N_EDGES];
__device__ float g_T[N_EDGES];
__device__ float g_Tperm[N_EDGES];
__device__ int   g_counts[N_NODES];
__device__ int   g_rowptr[N_NODES+1];
__device__ int   g_cursor[N_NODES];
__device__ int   g_srcs[N_EDGES];
__device__ int   g_eids[N_EDGES];
__device__ double g_sum, g_sumsq;
__device__ float  g_pmin, g_pmax;
__device__ float  g_mean, g_invstd, g_csum;
__device__ double g_Ssum[32];
__device__ unsigned int g_barc;
__device__ volatile unsigned int g_barg;
__device__ double g_colsum[EMB];

// ---------------- init ----------------
__global__ void init_kernel() {
    int i = blockIdx.x*blockDim.x + threadIdx.x;
    int nt = gridDim.x*blockDim.x;
    for (int k = i; k < N_NODES; k += nt) { g_counts[k] = 0; g_cursor[k] = 0; }
    if (i < EMB) g_colsum[i] = 0.0;
    if (i < 32)  g_Ssum[i]   = 0.0;
    if (i == 0) {
        g_sum = 0.0; g_sumsq = 0.0;
        g_pmin =  3.0e38f; g_pmax = -3.0e38f;
        g_barc = 0u; g_barg = 0u;
    }
}

// ---------------- CSR build ----------------
__global__ void hist_kernel(const int* __restrict__ dst) {
    int i = blockIdx.x*blockDim.x + threadIdx.x;
    int nt = gridDim.x*blockDim.x;
    for (int e = i; e < N_EDGES; e += nt) atomicAdd(&g_counts[dst[e]], 1);
}

__global__ void scan_kernel() {
    __shared__ int s[1024];
    const int CH = (N_NODES + 1023) / 1024;  // 20
    int t = threadIdx.x;
    int lsum = 0;
    for (int i = 0; i < CH; i++) {
        int idx = t*CH + i;
        if (idx < N_NODES) lsum += g_counts[idx];
    }
    s[t] = lsum; __syncthreads();
    for (int off = 1; off < 1024; off <<= 1) {
        int v = (t >= off) ? s[t-off] : 0;
        __syncthreads();
        s[t] += v;
        __syncthreads();
    }
    int run = s[t] - lsum;   // exclusive prefix
    for (int i = 0; i < CH; i++) {
        int idx = t*CH + i;
        if (idx < N_NODES) { g_rowptr[idx] = run; run += g_counts[idx]; }
    }
    if (t == 1023) g_rowptr[N_NODES] = s[1023];
}

__global__ void fill_kernel(const int* __restrict__ src, const int* __restrict__ dst) {
    int i = blockIdx.x*blockDim.x + threadIdx.x;
    int nt = gridDim.x*blockDim.x;
    for (int e = i; e < N_EDGES; e += nt) {
        int d = dst[e];
        int pos = atomicAdd(&g_cursor[d], 1);
        int slot = g_rowptr[d] + pos;
        g_srcs[slot] = src[e];
        g_eids[slot] = e;
    }
}

// ---------------- permute T into CSR slot order ----------------
__global__ void permT_kernel() {
    int i = blockIdx.x*blockDim.x + threadIdx.x;
    int nt = gridDim.x*blockDim.x;
    for (; i < N_EDGES; i += nt) g_Tperm[i] = g_T[g_eids[i]];
}

// ---------------- aggregation: warp per node, float4, unroll 4 ----------------
// Tw (if non-null) is in CSR SLOT order (g_Tperm).
__global__ void agg_kernel(const float* __restrict__ h, float* __restrict__ out,
                           const float* __restrict__ Tw, int dim) {
    int warp = threadIdx.x >> 5, lane = threadIdx.x & 31;
    int n = blockIdx.x * 8 + warp;
    if (n >= N_NODES) return;
    int vdim = dim >> 2;
    bool active = lane < vdim;
    const float4* __restrict__ h4 = (const float4*)h;
    int beg = g_rowptr[n], end = g_rowptr[n+1];
    float4 a0 = {0,0,0,0}, a1 = a0, a2 = a0, a3 = a0;
    int j = beg;
    for (; j + 4 <= end; j += 4) {
        int s0 = g_srcs[j], s1 = g_srcs[j+1], s2 = g_srcs[j+2], s3 = g_srcs[j+3];
        float w0 = 1.f, w1 = 1.f, w2 = 1.f, w3 = 1.f;
        if (Tw) { w0 = Tw[j]; w1 = Tw[j+1]; w2 = Tw[j+2]; w3 = Tw[j+3]; }
        if (active) {
            float4 v0 = h4[s0*vdim + lane];
            float4 v1 = h4[s1*vdim + lane];
            float4 v2 = h4[s2*vdim + lane];
            float4 v3 = h4[s3*vdim + lane];
            a0.x = fmaf(w0, v0.x, a0.x); a0.y = fmaf(w0, v0.y, a0.y);
            a0.z = fmaf(w0, v0.z, a0.z); a0.w = fmaf(w0, v0.w, a0.w);
            a1.x = fmaf(w1, v1.x, a1.x); a1.y = fmaf(w1, v1.y, a1.y);
            a1.z = fmaf(w1, v1.z, a1.z); a1.w = fmaf(w1, v1.w, a1.w);
            a2.x = fmaf(w2, v2.x, a2.x); a2.y = fmaf(w2, v2.y, a2.y);
            a2.z = fmaf(w2, v2.z, a2.z); a2.w = fmaf(w2, v2.w, a2.w);
            a3.x = fmaf(w3, v3.x, a3.x); a3.y = fmaf(w3, v3.y, a3.y);
            a3.z = fmaf(w3, v3.z, a3.z); a3.w = fmaf(w3, v3.w, a3.w);
        }
    }
    for (; j < end; j++) {
        int s0 = g_srcs[j];
        float w0 = Tw ? Tw[j] : 1.f;
        if (active) {
            float4 v0 = h4[s0*vdim + lane];
            a0.x = fmaf(w0, v0.x, a0.x); a0.y = fmaf(w0, v0.y, a0.y);
            a0.z = fmaf(w0, v0.z, a0.z); a0.w = fmaf(w0, v0.w, a0.w);
        }
    }
    a0.x += a1.x + a2.x + a3.x;
    a0.y += a1.y + a2.y + a3.y;
    a0.z += a1.z + a2.z + a3.z;
    a0.w += a1.w + a2.w + a3.w;
    if (active) ((float4*)out)[n*vdim + lane] = a0;
}

// ---------------- GEMM: C = maybe_relu((X [+Y]) @ W [+bias]) ----------------
// BM=BN=128, BK=16, 256 threads, TM=TN=8 (split 4+4), smem double-buffered.
#define GBM 128
#define GBN 128
#define GBK 16

__global__ __launch_bounds__(256, 2)
void gemm128(const float* __restrict__ X, const float* __restrict__ Y,
             const float* __restrict__ W, const float* __restrict__ bias,
             float* __restrict__ C, int M, int K, int N, int do_relu) {
    __shared__ float Xs[2][GBK][GBM];   // [k][m]
    __shared__ float Ws[2][GBK][GBN];   // [k][n]
    const int tid = threadIdx.x;
    const int tx = tid & 15, ty = tid >> 4;
    const int row0 = blockIdx.y * GBM;
    const int col0 = blockIdx.x * GBN;

    float acc[8][8];
#pragma unroll
    for (int i = 0; i < 8; i++)
#pragma unroll
        for (int j = 0; j < 8; j++) acc[i][j] = 0.f;

    float4 xv[2], wv[2];

    // ---- load one K-tile into registers ----
    auto load_tile = [&](int k0) {
#pragma unroll
        for (int i = 0; i < 2; i++) {
            int li = tid + i*256;              // 0..511
            int m  = li >> 2;                  // 0..127
            int kq = li & 3;                   // 0..3  (covers k = kq*4..kq*4+3)
            int gr = row0 + m;
            float4 v = {0.f,0.f,0.f,0.f};
            if (gr < M) {
                v = *reinterpret_cast<const float4*>(X + (size_t)gr*K + k0 + kq*4);
                if (Y) {
                    float4 y = *reinterpret_cast<const float4*>(Y + (size_t)gr*K + k0 + kq*4);
                    v.x += y.x; v.y += y.y; v.z += y.z; v.w += y.w;
                }
            }
            xv[i] = v;
            int r = li >> 5;                   // 0..15
            int c = (li & 31) * 4;             // 0..124
            wv[i] = *reinterpret_cast<const float4*>(W + (size_t)(k0 + r)*N + col0 + c);
        }
    };
    // ---- store registers into smem stage s ----
    auto store_tile = [&](int s) {
#pragma unroll
        for (int i = 0; i < 2; i++) {
            int li = tid + i*256;
            int m  = li >> 2;
            int kq = li & 3;
            Xs[s][kq*4+0][m] = xv[i].x;
            Xs[s][kq*4+1][m] = xv[i].y;
            Xs[s][kq*4+2][m] = xv[i].z;
            Xs[s][kq*4+3][m] = xv[i].w;
            int r = li >> 5;
            int c = (li & 31) * 4;
            *reinterpret_cast<float4*>(&Ws[s][r][c]) = wv[i];
        }
    };

    load_tile(0);
    store_tile(0);
    __syncthreads();

    int cur = 0;
    for (int k0 = 0; k0 < K; k0 += GBK) {
        bool has_next = (k0 + GBK < K);
        if (has_next) load_tile(k0 + GBK);
#pragma unroll
        for (int kk = 0; kk < GBK; kk++) {
            float a[8], b[8];
            *reinterpret_cast<float4*>(&a[0]) = *reinterpret_cast<const float4*>(&Xs[cur][kk][ty*4]);
            *reinterpret_cast<float4*>(&a[4]) = *reinterpret_cast<const float4*>(&Xs[cur][kk][64 + ty*4]);
            *reinterpret_cast<float4*>(&b[0]) = *reinterpret_cast<const float4*>(&Ws[cur][kk][tx*4]);
            *reinterpret_cast<float4*>(&b[4]) = *reinterpret_cast<const float4*>(&Ws[cur][kk][64 + tx*4]);
#pragma unroll
            for (int i = 0; i < 8; i++)
#pragma unroll
                for (int j = 0; j < 8; j++) acc[i][j] = fmaf(a[i], b[j], acc[i][j]);
        }
        if (has_next) {
            store_tile(cur ^ 1);
            __syncthreads();
            cur ^= 1;
        }
    }

    // ---- epilogue ----
    float bv[8];
    if (bias) {
        *reinterpret_cast<float4*>(&bv[0]) = *reinterpret_cast<const float4*>(bias + col0 + tx*4);
        *reinterpret_cast<float4*>(&bv[4]) = *reinterpret_cast<const float4*>(bias + col0 + 64 + tx*4);
    } else {
#pragma unroll
        for (int j = 0; j < 8; j++) bv[j] = 0.f;
    }
#pragma unroll
    for (int ih = 0; ih < 2; ih++) {
#pragma unroll
        for (int ii = 0; ii < 4; ii++) {
            int i = ih*4 + ii;
            int gr = row0 + ih*64 + ty*4 + ii;
            if (gr < M) {
#pragma unroll
                for (int jh = 0; jh < 2; jh++) {
                    float4 o;
                    float v0 = acc[i][jh*4+0] + bv[jh*4+0];
                    float v1 = acc[i][jh*4+1] + bv[jh*4+1];
                    float v2 = acc[i][jh*4+2] + bv[jh*4+2];
                    float v3 = acc[i][jh*4+3] + bv[jh*4+3];
                    if (do_relu) {
                        v0 = fmaxf(v0, 0.f); v1 = fmaxf(v1, 0.f);
                        v2 = fmaxf(v2, 0.f); v3 = fmaxf(v3, 0.f);
                    }
                    o.x = v0; o.y = v1; o.z = v2; o.w = v3;
                    *reinterpret_cast<float4*>(C + (size_t)gr*N + col0 + jh*64 + tx*4) = o;
                }
            }
        }
    }
}

// ---------------- edge attention: pe[e] = relu(A[src]+B[dst]+b1) . W2 + b2 ----------------
__global__ void edge_pe_kernel(const int* __restrict__ src, const int* __restrict__ dst,
                               const float* __restrict__ b1, const float* __restrict__ W2,
                               const float* __restrict__ b2) {
    int gid = blockIdx.x*blockDim.x + threadIdx.x;
    int lane = threadIdx.x & 31;
    int warp = gid >> 5;
    int nwarps = (gridDim.x*blockDim.x) >> 5;
    for (int e = warp; e < N_EDGES; e += nwarps) {
        int s = src[e], d = dst[e];
        const float4* Ap = reinterpret_cast<const float4*>(&g_Afac[s*HID]);
        const float4* Bp = reinterpret_cast<const float4*>(&g_Bfac[d*HID]);
        const float4* b1p = reinterpret_cast<const float4*>(b1);
        const float4* W2p = reinterpret_cast<const float4*>(W2);
        float acc = 0.f;
#pragma unroll
        for (int j = 0; j < 4; j++) {
            int idx = lane + 32*j;
            float4 a = Ap[idx], b = Bp[idx], bb = b1p[idx], w = W2p[idx];
            float z0 = fmaxf(a.x + b.x + bb.x, 0.f);
            float z1 = fmaxf(a.y + b.y + bb.y, 0.f);
            float z2 = fmaxf(a.z + b.z + bb.z, 0.f);
            float z3 = fmaxf(a.w + b.w + bb.w, 0.f);
            acc += z0*w.x + z1*w.y + z2*w.z + z3*w.w;
        }
#pragma unroll
        for (int off = 16; off > 0; off >>= 1)
            acc += __shfl_xor_sync(0xffffffffu, acc, off);
        if (lane == 0) g_pe[e] = acc + b2[0];
    }
}

// ---------------- pe stats ----------------
__device__ void atomicMaxF(float* addr, float v) {
    int* ai = (int*)addr; int old = *ai;
    while (__int_as_float(old) < v) {
        int assumed = old;
        old = atomicCAS(ai, assumed, __float_as_int(v));
        if (old == assumed) break;
    }
}
__device__ void atomicMinF(float* addr, float v) {
    int* ai = (int*)addr; int old = *ai;
    while (__int_as_float(old) > v) {
        int assumed = old;
        old = atomicCAS(ai, assumed, __float_as_int(v));
        if (old == assumed) break;
    }
}

__global__ void stats_kernel() {
    __shared__ double ssum[256], ssq[256];
    __shared__ float smn[256], smx[256];
    int i = blockIdx.x*blockDim.x + threadIdx.x;
    int nt = gridDim.x*blockDim.x;
    double lsum = 0.0, lsq = 0.0;
    float mn = 3.0e38f, mx = -3.0e38f;
    for (int e = i; e < N_EDGES; e += nt) {
        float p = g_pe[e];
        lsum += p; lsq += (double)p*p;
        mn = fminf(mn, p); mx = fmaxf(mx, p);
    }
    int t = threadIdx.x;
    ssum[t] = lsum; ssq[t] = lsq; smn[t] = mn; smx[t] = mx;
    __syncthreads();
    for (int off = 128; off > 0; off >>= 1) {
        if (t < off) {
            ssum[t] += ssum[t+off]; ssq[t] += ssq[t+off];
            smn[t] = fminf(smn[t], smn[t+off]); smx[t] = fmaxf(smx[t], smx[t+off]);
        }
        __syncthreads();
    }
    if (t == 0) {
        atomicAdd(&g_sum, ssum[0]);
        atomicAdd(&g_sumsq, ssq[0]);
        atomicMinF(&g_pmin, smn[0]);
        atomicMaxF(&g_pmax, smx[0]);
    }
}

__global__ void finalize_kernel() {
    double mean = g_sum / (double)N_EDGES;
    double var = (g_sumsq - g_sum*g_sum/(double)N_EDGES) / (double)(N_EDGES - 1);
    double istd = 1.0 / sqrt(var);
    g_mean = (float)mean;
    g_invstd = (float)istd;
    g_csum = (float)(((double)g_pmin + (double)g_pmax - 2.0*mean) * istd);  // s_min + s_max (standardized)
}

// ---------------- delta0 = 2*(atts + gumbel) - (s_min+s_max) ----------------
__global__ void delta0_kernel(const float* __restrict__ u) {
    int i = blockIdx.x*blockDim.x + threadIdx.x;
    int nt = gridDim.x*blockDim.x;
    float mean = g_mean, istd = g_invstd, cs = g_csum;
    for (int e = i; e < N_EDGES; e += nt) {
        float att = (g_pe[e] - mean) * istd;
        float g = -logf(-logf(u[e] + EPSF) + EPSF);
        float d = att + g;            // NOISE = 1
        g_delta0[e] = 2.f*d - cs;     // TEMP = 1
    }
}

// ---------------- Sinkhorn (collapsed to scalar-offset iteration) ----------------
#define SK_BLOCKS 132
#define SK_THREADS 256
#define SK_PER 10

__global__ void sinkhorn_kernel() {
    const int stride = SK_BLOCKS * SK_THREADS;
    const int tid = blockIdx.x*blockDim.x + threadIdx.x;
    float dv[SK_PER];
#pragma unroll
    for (int i = 0; i < SK_PER; i++) {
        int e = tid + i*stride;
        dv[i] = (e < N_EDGES) ? g_delta0[e] : -1.0e30f;  // sigmoid -> 0 for pad
    }
    __shared__ double sred[SK_THREADS];
    double K = 0.0;
    double Sfin = 0.0;
    for (int it = 0; it < 30; it++) {
        float Kf = (float)K;
        double s = 0.0;
#pragma unroll
        for (int i = 0; i < SK_PER; i++)
            s += 1.0f / (1.0f + __expf(-(dv[i] + Kf)));
        sred[threadIdx.x] = s;
        __syncthreads();
        for (int off = SK_THREADS/2; off > 0; off >>= 1) {
            if (threadIdx.x < off) sred[threadIdx.x] += sred[threadIdx.x + off];
            __syncthreads();
        }
        if (threadIdx.x == 0) atomicAdd(&g_Ssum[it], sred[0]);
        // grid barrier, generation it+1
        __threadfence();
        __syncthreads();
        if (threadIdx.x == 0) {
            unsigned my = atomicAdd(&g_barc, 1u);
            if (my == SK_BLOCKS - 1) {
                g_barc = 0u;
                __threadfence();
                g_barg = (unsigned)(it + 1);
            } else {
                while (g_barg < (unsigned)(it + 1)) { }
            }
        }
        __syncthreads();
        __threadfence();
        double S1 = ((volatile double*)g_Ssum)[it];
        if (it == 29) { Sfin = S1; break; }
        double S0 = (double)N_EDGES - S1;
        K += log(S0 / S1) + log(RATIO_F / (1.0 - RATIO_F));
        __syncthreads();
    }
    float Kf = (float)K;
    float scale = (float)(((double)N_EDGES * RATIO_F) / Sfin);  // exp(r1)/S1_final
#pragma unroll
    for (int i = 0; i < SK_PER; i++) {
        int e = tid + i*stride;
        if (e < N_EDGES)
            g_T[e] = scale / (1.f + __expf(-(dv[i] + Kf)));
    }
}

// ---------------- mean pool + head ----------------
__global__ void colsum_kernel(const float* __restrict__ h) {
    int t = threadIdx.x;  // 128
    double acc = 0.0;
    for (int r = blockIdx.x; r < N_NODES; r += gridDim.x)
        acc += h[r*EMB + t];
    atomicAdd(&g_colsum[t], acc);
}

__global__ void head_kernel(const float* __restrict__ head_W,
                            const float* __restrict__ head_b,
                            float* __restrict__ out) {
    __shared__ float rep[EMB];
    int t = threadIdx.x;
    rep[t] = (float)(g_colsum[t] / (double)N_NODES);
    __syncthreads();
    if (t < OUT_DIM) {
        float a = head_b[t];
        for (int d = 0; d < EMB; d++) a += rep[d] * head_W[d*OUT_DIM + t];
        out[t] = a;
    }
}

// ---------------- launch ----------------
extern "C" void kernel_launch(void* const* d_in, const int* in_sizes, int n_in,
                              void* d_out, int out_size) {
    const float* x       = (const float*)d_in[0];
    const int*   ei      = (const int*)  d_in[1];
    const float* u       = (const float*)d_in[2];
    const float* enc_W0  = (const float*)d_in[3];
    const float* enc_b0  = (const float*)d_in[4];
    const float* enc_W   = (const float*)d_in[5];
    const float* enc_b   = (const float*)d_in[6];
    const float* ea_W1   = (const float*)d_in[7];
    const float* ea_b1   = (const float*)d_in[8];
    const float* ea_W2   = (const float*)d_in[9];
    const float* ea_b2   = (const float*)d_in[10];
    const float* cls_W0  = (const float*)d_in[11];
    const float* cls_b0  = (const float*)d_in[12];
    const float* cls_W   = (const float*)d_in[13];
    const float* cls_b   = (const float*)d_in[14];
    const float* head_W  = (const float*)d_in[15];
    const float* head_b  = (const float*)d_in[16];
    const int* src = ei;
    const int* dst = ei + N_EDGES;

    // GB300/ATS: __device__ symbols passed as kernel args from host code decay
    // to the HOST shadow address. Resolve real device addresses explicitly.
    float *p_h0, *p_h1, *p_agg, *p_Afac, *p_Bfac, *p_Tperm;
    cudaGetSymbolAddress((void**)&p_h0,    g_h0);
    cudaGetSymbolAddress((void**)&p_h1,    g_h1);
    cudaGetSymbolAddress((void**)&p_agg,   g_agg);
    cudaGetSymbolAddress((void**)&p_Afac,  g_Afac);
    cudaGetSymbolAddress((void**)&p_Bfac,  g_Bfac);
    cudaGetSymbolAddress((void**)&p_Tperm, g_Tperm);

    const dim3 gemm_grid128(1, (N_NODES + GBM - 1)/GBM);  // N=128
    const dim3 gemm_grid512(HID/GBN, (N_NODES + GBM - 1)/GBM);  // N=512
    const int  agg_blocks = (N_NODES + 7) / 8;

    init_kernel<<<80, 256>>>();
    hist_kernel<<<640, 256>>>(dst);
    scan_kernel<<<1, 1024>>>();
    fill_kernel<<<640, 256>>>(src, dst);

    // ----- encoder GIN stack (att = 1) -----
    agg_kernel<<<agg_blocks, 256>>>(x, p_agg, nullptr, IN_DIM);
    gemm128<<<gemm_grid128, 256>>>(x, p_agg, enc_W0, enc_b0, p_h0,
                                   N_NODES, IN_DIM, EMB, 1);
    float* hcur = p_h0; float* hnxt = p_h1;
    for (int l = 0; l < 4; l++) {
        agg_kernel<<<agg_blocks, 256>>>(hcur, p_agg, nullptr, EMB);
        gemm128<<<gemm_grid128, 256>>>(hcur, p_agg, enc_W + l*EMB*EMB,
                                       enc_b + l*EMB, hnxt,
                                       N_NODES, EMB, EMB, 1);
        float* t = hcur; hcur = hnxt; hnxt = t;
    }

    // ----- edge attention (factored): A = h@W1[:128], B = h@W1[128:] -----
    gemm128<<<gemm_grid512, 256>>>(hcur, nullptr, ea_W1, nullptr, p_Afac,
                                   N_NODES, EMB, HID, 0);
    gemm128<<<gemm_grid512, 256>>>(hcur, nullptr, ea_W1 + EMB*HID, nullptr, p_Bfac,
                                   N_NODES, EMB, HID, 0);
    edge_pe_kernel<<<2000, 256>>>(src, dst, ea_b1, ea_W2, ea_b2);

    stats_kernel<<<640, 256>>>();
    finalize_kernel<<<1, 1>>>();
    delta0_kernel<<<640, 256>>>(u);
    sinkhorn_kernel<<<SK_BLOCKS, SK_THREADS>>>();
    permT_kernel<<<640, 256>>>();

    // ----- classifier GIN stack (att = T, CSR-permuted) -----
    agg_kernel<<<agg_blocks, 256>>>(x, p_agg, p_Tperm, IN_DIM);
    gemm128<<<gemm_grid128, 256>>>(x, p_agg, cls_W0, cls_b0, p_h0,
                                   N_NODES, IN_DIM, EMB, 1);
    hcur = p_h0; hnxt = p_h1;
    for (int l = 0; l < 4; l++) {
        agg_kernel<<<agg_blocks, 256>>>(hcur, p_agg, p_Tperm, EMB);
        gemm128<<<gemm_grid128, 256>>>(hcur, p_agg, cls_W + l*EMB*EMB,
                                       cls_b + l*EMB, hnxt,
                                       N_NODES, EMB, EMB, 1);
        float* t = hcur; hcur = hnxt; hnxt = t;
    }

    // ----- mean pool + head -----
    colsum_kernel<<<160, EMB>>>(hcur);
    head_kernel<<<1, EMB>>>(head_W, head_b, (float*)d_out);
}